// round 4
// baseline (speedup 1.0000x reference)
#include <cuda_runtime.h>

#define HID 64
#define NB 65536

__device__ float g_x[(size_t)NB * HID];   // conv output [B,64]

// ========================= conv kernel =========================
__global__ __launch_bounds__(128) void conv_k(
    const float* __restrict__ obs,
    const float* __restrict__ w1, const float* __restrict__ b1,
    const float* __restrict__ w2, const float* __restrict__ b2,
    const float* __restrict__ w3, const float* __restrict__ b3)
{
    __shared__ float sw1[192], sb1[16], sw2[2048], sb2[32], sw3[8192], sb3[64];
    const int t = threadIdx.x;
    for (int i = t; i < 192;  i += 128) sw1[i] = w1[i];
    for (int i = t; i < 16;   i += 128) sb1[i] = b1[i];
    for (int i = t; i < 2048; i += 128) sw2[i] = w2[i];
    for (int i = t; i < 32;   i += 128) sb2[i] = b2[i];
    for (int i = t; i < 8192; i += 128) sw3[i] = w3[i];
    for (int i = t; i < 64;   i += 128) sb3[i] = b3[i];
    __syncthreads();

    const size_t b = (size_t)blockIdx.x * 128 + t;
    const float* ob = obs + b * 147;      // [7,7,3] NHWC
    float o[147];
    #pragma unroll 21
    for (int i = 0; i < 147; i++) o[i] = __ldg(ob + i);

    // conv1(16,3,2,2) + relu + maxpool2 -> p[16][3][3]
    float p[144];
    for (int oc = 0; oc < 16; oc++) {
        const float bias = sb1[oc];
        const float* w = sw1 + oc * 12;
        #pragma unroll
        for (int pi = 0; pi < 3; pi++)
        #pragma unroll
        for (int pj = 0; pj < 3; pj++) {
            float mx = -1e30f;
            #pragma unroll
            for (int di = 0; di < 2; di++)
            #pragma unroll
            for (int dj = 0; dj < 2; dj++) {
                const int i0 = 2 * pi + di, j0 = 2 * pj + dj;
                float acc = bias;
                #pragma unroll
                for (int ic = 0; ic < 3; ic++)
                #pragma unroll
                for (int a = 0; a < 2; a++)
                #pragma unroll
                for (int c = 0; c < 2; c++)
                    acc += o[((i0 + a) * 7 + (j0 + c)) * 3 + ic] * w[ic * 4 + a * 2 + c];
                mx = fmaxf(mx, acc);
            }
            p[oc * 9 + pi * 3 + pj] = fmaxf(mx, 0.f);  // relu(max)==max(relu)
        }
    }

    // conv2(32,16,2,2) + relu -> q[32][2][2]
    float q[128];
    for (int oc = 0; oc < 32; oc++) {
        float a0 = sb2[oc], a1 = a0, a2 = a0, a3 = a0;
        #pragma unroll 4
        for (int ic = 0; ic < 16; ic++) {
            const float* pr = p + ic * 9;
            const float* w = sw2 + (oc * 16 + ic) * 4;
            a0 += pr[0]*w[0] + pr[1]*w[1] + pr[3]*w[2] + pr[4]*w[3];
            a1 += pr[1]*w[0] + pr[2]*w[1] + pr[4]*w[2] + pr[5]*w[3];
            a2 += pr[3]*w[0] + pr[4]*w[1] + pr[6]*w[2] + pr[7]*w[3];
            a3 += pr[4]*w[0] + pr[5]*w[1] + pr[7]*w[2] + pr[8]*w[3];
        }
        q[oc*4+0] = fmaxf(a0, 0.f); q[oc*4+1] = fmaxf(a1, 0.f);
        q[oc*4+2] = fmaxf(a2, 0.f); q[oc*4+3] = fmaxf(a3, 0.f);
    }

    // conv3(64,32,2,2) + relu -> x[64]
    for (int oc = 0; oc < 64; oc++) {
        float acc = sb3[oc];
        const float* w = sw3 + oc * 128;
        #pragma unroll 16
        for (int i = 0; i < 128; i++) acc += q[i] * w[i];
        g_x[b * 64 + oc] = fmaxf(acc, 0.f);
    }
}

// ========================= GRU + heads kernel =========================
#define NT 256
#define ROW 65
#define SWOFF (NT * ROW)                  // 16640 floats
#define SMEM_FLOATS (SWOFF + 24960)       // +wih 12288 +whh 12288 +biases 384
#define SMEM_BYTES (SMEM_FLOATS * 4)      // 166400 bytes

__device__ __forceinline__ float sigm(float x) { return 1.f / (1.f + __expf(-x)); }

__device__ void load_layer(float* sw, const float* wih, const float* whh,
                           const float* bih, const float* bhh)
{
    const int t = threadIdx.x;
    for (int i = t; i < 3072; i += NT) ((float4*)sw)[i]           = ((const float4*)wih)[i];
    for (int i = t; i < 3072; i += NT) ((float4*)(sw + 12288))[i] = ((const float4*)whh)[i];
    for (int i = t; i < 48;   i += NT) ((float4*)(sw + 24576))[i] = ((const float4*)bih)[i];
    for (int i = t; i < 48;   i += NT) ((float4*)(sw + 24768))[i] = ((const float4*)bhh)[i];
}

// one GRU cell: x in regs, h from global, result left in shared `row`
__device__ void cell(const float xr[64], float* row, const float* sw,
                     const float* __restrict__ hin)
{
    float h[64];
    #pragma unroll
    for (int k = 0; k < 16; k++) {
        const float4 v = __ldg((const float4*)hin + k);
        h[4*k] = v.x; h[4*k+1] = v.y; h[4*k+2] = v.z; h[4*k+3] = v.w;
    }
    #pragma unroll
    for (int k = 0; k < 64; k++) row[k] = h[k];

    const float4* wih = (const float4*)sw;
    const float4* whh = (const float4*)(sw + 12288);
    const float* bih = sw + 24576;
    const float* bhh = sw + 24768;

    #pragma unroll 1
    for (int o = 0; o < 64; o++) {
        float ir = 0.f, iz = 0.f, in_ = 0.f, hr = 0.f, hz = 0.f, hn = 0.f;
        const float4* wr = wih + o * 16;
        const float4* wz = wih + (o + 64) * 16;
        const float4* wn = wih + (o + 128) * 16;
        const float4* vr = whh + o * 16;
        const float4* vz = whh + (o + 64) * 16;
        const float4* vn = whh + (o + 128) * 16;
        #pragma unroll
        for (int k = 0; k < 16; k++) {
            const float4 A = wr[k], Bv = wz[k], C = wn[k];
            const float4 D = vr[k], E = vz[k], F = vn[k];
            const float x0 = xr[4*k], x1 = xr[4*k+1], x2 = xr[4*k+2], x3 = xr[4*k+3];
            const float h0 = h[4*k],  h1 = h[4*k+1],  h2 = h[4*k+2],  h3 = h[4*k+3];
            ir  += x0*A.x  + x1*A.y  + x2*A.z  + x3*A.w;
            iz  += x0*Bv.x + x1*Bv.y + x2*Bv.z + x3*Bv.w;
            in_ += x0*C.x  + x1*C.y  + x2*C.z  + x3*C.w;
            hr  += h0*D.x  + h1*D.y  + h2*D.z  + h3*D.w;
            hz  += h0*E.x  + h1*E.y  + h2*E.z  + h3*E.w;
            hn  += h0*F.x  + h1*F.y  + h2*F.z  + h3*F.w;
        }
        const float r = sigm(ir + bih[o]      + hr + bhh[o]);
        const float z = sigm(iz + bih[o + 64] + hz + bhh[o + 64]);
        const float n = tanhf(in_ + bih[o + 128] + r * (hn + bhh[o + 128]));
        const float ho = row[o];
        row[o] = (1.f - z) * n + z * ho;
    }
}

__device__ void flush(const float* row, float* gout, float xr[64])
{
    #pragma unroll
    for (int k = 0; k < 16; k++) {
        const float4 v = make_float4(row[4*k], row[4*k+1], row[4*k+2], row[4*k+3]);
        ((float4*)gout)[k] = v;
        xr[4*k] = v.x; xr[4*k+1] = v.y; xr[4*k+2] = v.z; xr[4*k+3] = v.w;
    }
}

__global__ __launch_bounds__(NT, 1) void gru_k(
    const float* __restrict__ memory,
    const float* g10a, const float* g10b, const float* g10c, const float* g10d,
    const float* g11a, const float* g11b, const float* g11c, const float* g11d,
    const float* g20a, const float* g20b, const float* g20c, const float* g20d,
    const float* g21a, const float* g21b, const float* g21c, const float* g21d,
    const float* aw1, const float* ab1, const float* aw2, const float* ab2,
    const float* cw1, const float* cb1, const float* cw2, const float* cb2,
    float* __restrict__ out)
{
    extern __shared__ float s[];
    const int t = threadIdx.x;
    const size_t b = (size_t)blockIdx.x * NT + t;
    float* row = s + t * ROW;
    float* sw = s + SWOFF;

    float xr[64];
    #pragma unroll
    for (int k = 0; k < 16; k++) {
        const float4 v = __ldg((const float4*)(g_x + b * 64) + k);
        xr[4*k] = v.x; xr[4*k+1] = v.y; xr[4*k+2] = v.z; xr[4*k+3] = v.w;
    }
    const float* mrow = memory + b * 256;
    float* orow = out + (size_t)NB * 4 + b * 256;

    load_layer(sw, g10a, g10b, g10c, g10d);  __syncthreads();
    cell(xr, row, sw, mrow);         flush(row, orow, xr);
    __syncthreads(); load_layer(sw, g11a, g11b, g11c, g11d); __syncthreads();
    cell(xr, row, sw, mrow + 64);    flush(row, orow + 64, xr);
    __syncthreads(); load_layer(sw, g20a, g20b, g20c, g20d); __syncthreads();
    cell(xr, row, sw, mrow + 128);   flush(row, orow + 128, xr);
    __syncthreads(); load_layer(sw, g21a, g21b, g21c, g21d); __syncthreads();
    cell(xr, row, sw, mrow + 192);   flush(row, orow + 192, xr);
    __syncthreads();

    // stage head weights: aw1@0 ab1@4096 aw2@4160 ab2@4352 cw1@4355 cb1@8451 cw2@8515 cb2@8579
    for (int i = t; i < 4096; i += NT) sw[i] = aw1[i];
    for (int i = t; i < 64;   i += NT) sw[4096 + i] = ab1[i];
    for (int i = t; i < 192;  i += NT) sw[4160 + i] = aw2[i];
    if (t < 3) sw[4352 + t] = ab2[t];
    for (int i = t; i < 4096; i += NT) sw[4355 + i] = cw1[i];
    for (int i = t; i < 64;   i += NT) sw[8451 + i] = cb1[i];
    for (int i = t; i < 64;   i += NT) sw[8515 + i] = cw2[i];
    if (t == 0) sw[8579] = cb2[0];
    __syncthreads();

    // actor hidden + logits + log_softmax
    #pragma unroll 1
    for (int o = 0; o < 64; o++) {
        float acc = sw[4096 + o];
        const float* w = sw + o * 64;
        #pragma unroll
        for (int k = 0; k < 64; k++) acc += xr[k] * w[k];
        row[o] = fmaxf(acc, 0.f);
    }
    float lg[3];
    #pragma unroll
    for (int j = 0; j < 3; j++) {
        float acc = sw[4352 + j];
        const float* w = sw + 4160 + j * 64;
        for (int k = 0; k < 64; k++) acc += row[k] * w[k];
        lg[j] = acc;
    }
    const float m = fmaxf(lg[0], fmaxf(lg[1], lg[2]));
    const float lse = m + logf(__expf(lg[0]-m) + __expf(lg[1]-m) + __expf(lg[2]-m));
    out[b*3+0] = lg[0]-lse; out[b*3+1] = lg[1]-lse; out[b*3+2] = lg[2]-lse;

    // critic
    #pragma unroll 1
    for (int o = 0; o < 64; o++) {
        float acc = sw[8451 + o];
        const float* w = sw + 4355 + o * 64;
        #pragma unroll
        for (int k = 0; k < 64; k++) acc += xr[k] * w[k];
        row[o] = fmaxf(acc, 0.f);
    }
    float v = sw[8579];
    for (int k = 0; k < 64; k++) v += row[k] * sw[8515 + k];
    out[(size_t)NB * 3 + b] = v;
}

extern "C" void kernel_launch(void* const* d_in, const int* in_sizes, int n_in,
                              void* d_out, int out_size)
{
    const float* const* in = (const float* const*)d_in;
    conv_k<<<NB / 128, 128>>>(in[0], in[2], in[3], in[4], in[5], in[6], in[7]);
    cudaFuncSetAttribute(gru_k, cudaFuncAttributeMaxDynamicSharedMemorySize, SMEM_BYTES);
    gru_k<<<NB / NT, NT, SMEM_BYTES>>>(in[1],
        in[8],  in[9],  in[10], in[11],
        in[12], in[13], in[14], in[15],
        in[16], in[17], in[18], in[19],
        in[20], in[21], in[22], in[23],
        in[24], in[25], in[26], in[27],
        in[28], in[29], in[30], in[31],
        (float*)d_out);
}